// round 13
// baseline (speedup 1.0000x reference)
#include <cuda_runtime.h>
#include <cuda_fp16.h>
#include <cstdint>

#define MAX_N 100000
#define MAX_E 1700000
#define FDIM  128
#define CHUNK 1024

// Scratch (allocation-free: __device__ globals)
__device__ __half g_hA[(size_t)MAX_N * FDIM];   // H buffer A (fp16)
__device__ __half g_hB[(size_t)MAX_N * FDIM];   // H buffer B (fp16)
__device__ __half g_xh[(size_t)MAX_N * FDIM];   // converted input X (fp16)
__device__ __half g_wt[3 * FDIM * FDIM];        // W transposed [n][k], fp16
__device__ float g_dinv[MAX_N];
__device__ float g_dinv2[MAX_N];
__device__ int   g_cnt[MAX_N];
__device__ int   g_pos[MAX_N];
__device__ int   g_rowStart[MAX_N];
__device__ int   g_wcur[MAX_N];
__device__ int   g_chunkSum[128];
__device__ int2  g_epk[MAX_E];                  // packed (src, norm-bits)

// ---------------------------------------------------------------------------
__global__ void k_hist(const int* __restrict__ ei, int E) {
    int e = blockIdx.x * blockDim.x + threadIdx.x;
    if (e < E) atomicAdd(&g_cnt[ei[E + e]], 1);
}

__global__ __launch_bounds__(256) void k_scan1(int n) {
    __shared__ int sh[256];
    int t = threadIdx.x;
    int base = blockIdx.x * CHUNK + t * 4;
    int v0 = (base + 0 < n) ? g_cnt[base + 0] : 0;
    int v1 = (base + 1 < n) ? g_cnt[base + 1] : 0;
    int v2 = (base + 2 < n) ? g_cnt[base + 2] : 0;
    int v3 = (base + 3 < n) ? g_cnt[base + 3] : 0;
    int tsum = v0 + v1 + v2 + v3;
    sh[t] = tsum;
    __syncthreads();
    for (int off = 1; off < 256; off <<= 1) {
        int x = (t >= off) ? sh[t - off] : 0;
        __syncthreads();
        sh[t] += x;
        __syncthreads();
    }
    int texcl = sh[t] - tsum;
    if (base + 0 < n) g_pos[base + 0] = texcl;
    if (base + 1 < n) g_pos[base + 1] = texcl + v0;
    if (base + 2 < n) g_pos[base + 2] = texcl + v0 + v1;
    if (base + 3 < n) g_pos[base + 3] = texcl + v0 + v1 + v2;
    if (t == 255) g_chunkSum[blockIdx.x] = sh[255];
}

// Merged scan2+scan3.
__global__ __launch_bounds__(256) void k_scan23(int n, int nChunks) {
    __shared__ int cs[128];
    int t = threadIdx.x;
    if (t < 128) cs[t] = (t < nChunks) ? g_chunkSum[t] : 0;
    __syncthreads();
    if (t < 128) {
        for (int off = 1; off < 128; off <<= 1) {
            int x = (t >= off) ? cs[t - off] : 0;
            __syncthreads();
            cs[t] += x;
            __syncthreads();
        }
    } else {
        for (int off = 1; off < 128; off <<= 1) { __syncthreads(); __syncthreads(); }
    }
    int i = blockIdx.x * 256 + t;
    if (i < n) {
        int c = i / CHUNK;
        int chunkExcl = (c == 0) ? 0 : cs[c - 1];
        int rs = g_pos[i] + chunkExcl;
        g_rowStart[i] = rs;
        g_wcur[i]     = rs;
        float di = rsqrtf((float)g_cnt[i] + 1.0f);
        g_dinv[i]  = di;
        g_dinv2[i] = di * di;
    }
}

__global__ void k_build(const int* __restrict__ ei, int E) {
    int e = blockIdx.x * blockDim.x + threadIdx.x;
    if (e < E) {
        int s = ei[e];
        int d = ei[E + e];
        int p = atomicAdd(&g_wcur[d], 1);
        g_epk[p] = make_int2(s, __float_as_int(g_dinv[s] * g_dinv[d]));
    }
}

// ---------------------------------------------------------------------------
__global__ void k_convertX(const float* __restrict__ x, long long n8) {
    long long i = (long long)blockIdx.x * blockDim.x + threadIdx.x;
    if (i >= n8) return;
    const float4* xp = (const float4*)x + i * 2;
    float4 v0 = __ldg(xp), v1 = __ldg(xp + 1);
    float f[8] = {v0.x, v0.y, v0.z, v0.w, v1.x, v1.y, v1.z, v1.w};
    __half h[8];
#pragma unroll
    for (int j = 0; j < 8; j++) h[j] = __float2half_rn(f[j]);
    *(uint4*)&g_xh[i * 8] = *(uint4*)h;
}

__global__ void k_convertW(const float* __restrict__ W1,
                           const float* __restrict__ W2,
                           const float* __restrict__ W3) {
    int slot = blockIdx.x >> 6;
    const float* W = (slot == 0) ? W1 : (slot == 1) ? W2 : W3;
    int idx = ((blockIdx.x & 63) << 8) + threadIdx.x;
    int n = idx >> 7, k = idx & 127;
    g_wt[slot * FDIM * FDIM + idx] = __float2half_rn(__ldg(&W[k * FDIM + n]));
}

// ---------------------------------------------------------------------------
// MMA helpers
__device__ __forceinline__ void ldsm4(uint32_t* r, uint32_t addr) {
    asm volatile("ldmatrix.sync.aligned.m8n8.x4.shared.b16 {%0,%1,%2,%3}, [%4];"
        : "=r"(r[0]), "=r"(r[1]), "=r"(r[2]), "=r"(r[3]) : "r"(addr));
}
__device__ __forceinline__ void mma16816(float* c, const uint32_t* a, const uint32_t* b) {
    asm volatile(
        "mma.sync.aligned.m16n8k16.row.col.f32.f16.f16.f32 "
        "{%0,%1,%2,%3}, {%4,%5,%6,%7}, {%8,%9}, {%0,%1,%2,%3};"
        : "+f"(c[0]), "+f"(c[1]), "+f"(c[2]), "+f"(c[3])
        : "r"(a[0]), "r"(a[1]), "r"(a[2]), "r"(a[3]), "r"(b[0]), "r"(b[1]));
}

// Shared GEMM core: A[128][APK], B[128][APK] in smem; acc += A@B^T; store hdst.
#define APK 136

__device__ __forceinline__ void gemm_from_smem(
    const __half* a_s, const __half* b_s, __half* hdst, int rowbase, int N,
    int wid, int lane)
{
    int warp_m = wid & 3;
    int warp_n = wid >> 2;

    float acc[2][8][4];
#pragma unroll
    for (int i = 0; i < 2; i++)
#pragma unroll
        for (int j = 0; j < 8; j++)
#pragma unroll
            for (int q = 0; q < 4; q++) acc[i][j][q] = 0.f;

#pragma unroll
    for (int s = 0; s < 8; s++) {
        int kb = s * 16;
        uint32_t af[2][4];
#pragma unroll
        for (int mi = 0; mi < 2; mi++) {
            int mrow = warp_m * 32 + mi * 16 + (lane & 15);
            int kcol = kb + ((lane >> 4) << 3);
            ldsm4(af[mi], (uint32_t)__cvta_generic_to_shared(a_s + mrow * APK + kcol));
        }
        uint32_t bf[8][2];
#pragma unroll
        for (int nb = 0; nb < 4; nb++) {
            int nrow = warp_n * 64 + nb * 16 + ((lane >> 4) << 3) + (lane & 7);
            int kcol = kb + (((lane >> 3) & 1) << 3);
            uint32_t r[4];
            ldsm4(r, (uint32_t)__cvta_generic_to_shared(b_s + nrow * APK + kcol));
            bf[nb*2][0] = r[0]; bf[nb*2][1] = r[1];
            bf[nb*2+1][0] = r[2]; bf[nb*2+1][1] = r[3];
        }
#pragma unroll
        for (int mi = 0; mi < 2; mi++)
#pragma unroll
            for (int nj = 0; nj < 8; nj++)
                mma16816(acc[mi][nj], af[mi], bf[nj]);
    }

#pragma unroll
    for (int mi = 0; mi < 2; mi++) {
        int r0 = rowbase + warp_m * 32 + mi * 16 + (lane >> 2);
        int r1 = r0 + 8;
#pragma unroll
        for (int nj = 0; nj < 8; nj++) {
            int col = warp_n * 64 + nj * 8 + 2 * (lane & 3);
            if (r0 < N) {
                __half2 p = __floats2half2_rn(acc[mi][nj][0], acc[mi][nj][1]);
                *(__half2*)&hdst[(size_t)r0 * FDIM + col] = p;
            }
            if (r1 < N) {
                __half2 p = __floats2half2_rn(acc[mi][nj][2], acc[mi][nj][3]);
                *(__half2*)&hdst[(size_t)r1 * FDIM + col] = p;
            }
        }
    }
}

#define FUSED_SMEM (2 * 128 * APK * 2)   // 69632 B

// ---------------------------------------------------------------------------
// Layer-1 GEMM: X (converted fp16, global) @ W -> hdst. Loads A from global.
__global__ __launch_bounds__(256) void k_gemm1(
    const __half* __restrict__ Xh, const __half* __restrict__ Wt,
    __half* __restrict__ hdst, int N)
{
    extern __shared__ __half sm[];
    __half* a_s = sm;
    __half* b_s = sm + 128 * APK;

    int t = threadIdx.x, wid = t >> 5, lane = t & 31;
    int rowbase = blockIdx.x * 128;

#pragma unroll
    for (int i = 0; i < 8; i++) {
        int idx = t + i * 256;
        int row = idx >> 4;
        int k8  = (idx & 15) * 8;
        int grow = rowbase + row;
        uint4 v = (grow < N)
            ? *(const uint4*)&Xh[(size_t)grow * FDIM + k8]
            : make_uint4(0, 0, 0, 0);
        *(uint4*)&a_s[row * APK + k8] = v;
        *(uint4*)&b_s[row * APK + k8] = *(const uint4*)&Wt[(size_t)row * FDIM + k8];
    }
    __syncthreads();
    gemm_from_smem(a_s, b_s, hdst, rowbase, N, wid, lane);
}

// ---------------------------------------------------------------------------
// Fused: gather(hsrc)+bias+relu -> smem A (fp16); then A @ W -> hdst (fp16).
__global__ __launch_bounds__(256) void k_fused(
    const __half* __restrict__ hsrc, const float* __restrict__ bias,
    const __half* __restrict__ Wt, __half* __restrict__ hdst, int N)
{
    extern __shared__ __half sm[];
    __half* a_s = sm;
    __half* b_s = sm + 128 * APK;

    int t = threadIdx.x, wid = t >> 5, lane = t & 31;
    int rowbase = blockIdx.x * 128;

    // B fill (W tile, L1/L2-hot)
#pragma unroll
    for (int i = 0; i < 8; i++) {
        int idx = t + i * 256;
        int nrow = idx >> 4;
        int k8   = (idx & 15) * 8;
        *(uint4*)&b_s[nrow * APK + k8] = *(const uint4*)&Wt[(size_t)nrow * FDIM + k8];
    }

    // Gather phase: warp wid handles rows wid + 8*i, i = 0..15
    const float4 bb = __ldg((const float4*)bias + lane);
    for (int i = 0; i < 16; i++) {
        int r = wid + 8 * i;
        int grow = rowbase + r;
        if (grow < N) {
            int start = g_rowStart[grow];
            int cnt   = g_cnt[grow];
            float d2  = g_dinv2[grow];
            uint2 hv = __ldg((const uint2*)(hsrc + (size_t)grow * FDIM) + lane);
            float2 p0 = __half22float2(*(__half2*)&hv.x);
            float2 p1 = __half22float2(*(__half2*)&hv.y);
            float4 acc = make_float4(p0.x * d2, p0.y * d2, p1.x * d2, p1.y * d2);

            for (int e0 = 0; e0 < cnt; e0 += 32) {
                int mye = e0 + lane;
                int s = 0; float nm = 0.f;
                if (mye < cnt) {
                    int2 ep = __ldg(&g_epk[start + mye]);
                    s  = ep.x;
                    nm = __int_as_float(ep.y);
                }
                int m = min(32, cnt - e0);
#pragma unroll 8
                for (int j = 0; j < m; j++) {
                    int   sj = __shfl_sync(0xffffffffu, s,  j);
                    float nj = __shfl_sync(0xffffffffu, nm, j);
                    uint2 v = __ldg((const uint2*)(hsrc + (size_t)sj * FDIM) + lane);
                    float2 q0 = __half22float2(*(__half2*)&v.x);
                    float2 q1 = __half22float2(*(__half2*)&v.y);
                    acc.x = fmaf(q0.x, nj, acc.x);
                    acc.y = fmaf(q0.y, nj, acc.y);
                    acc.z = fmaf(q1.x, nj, acc.z);
                    acc.w = fmaf(q1.y, nj, acc.w);
                }
            }
            __half hh[4];
            hh[0] = __float2half_rn(fmaxf(acc.x + bb.x, 0.f));
            hh[1] = __float2half_rn(fmaxf(acc.y + bb.y, 0.f));
            hh[2] = __float2half_rn(fmaxf(acc.z + bb.z, 0.f));
            hh[3] = __float2half_rn(fmaxf(acc.w + bb.w, 0.f));
            *(uint2*)&a_s[r * APK + 4 * lane] = *(uint2*)hh;
        } else {
            *(uint2*)&a_s[r * APK + 4 * lane] = make_uint2(0, 0);
        }
    }
    __syncthreads();

    gemm_from_smem(a_s, b_s, hdst, rowbase, N, wid, lane);
}

// ---------------------------------------------------------------------------
// Final gather: fp32 out, + bias, no relu.
__global__ __launch_bounds__(256) void k_gather_out(
    const __half* __restrict__ h, const float* __restrict__ b,
    float* __restrict__ ofp, int N)
{
    int warp = (blockIdx.x * 256 + threadIdx.x) >> 5;
    int lane = threadIdx.x & 31;
    if (warp >= N) return;

    int row   = warp;
    int start = g_rowStart[row];
    int cnt   = g_cnt[row];

    float d2 = g_dinv2[row];
    uint2 hv = __ldg((const uint2*)(h + (size_t)row * FDIM) + lane);
    float2 p0 = __half22float2(*(__half2*)&hv.x);
    float2 p1 = __half22float2(*(__half2*)&hv.y);
    float4 acc = make_float4(p0.x * d2, p0.y * d2, p1.x * d2, p1.y * d2);

    for (int e0 = 0; e0 < cnt; e0 += 32) {
        int mye = e0 + lane;
        int s = 0; float nm = 0.f;
        if (mye < cnt) {
            int2 ep = __ldg(&g_epk[start + mye]);
            s  = ep.x;
            nm = __int_as_float(ep.y);
        }
        int m = min(32, cnt - e0);
#pragma unroll 8
        for (int j = 0; j < m; j++) {
            int   sj = __shfl_sync(0xffffffffu, s,  j);
            float nj = __shfl_sync(0xffffffffu, nm, j);
            uint2 v = __ldg((const uint2*)(h + (size_t)sj * FDIM) + lane);
            float2 q0 = __half22float2(*(__half2*)&v.x);
            float2 q1 = __half22float2(*(__half2*)&v.y);
            acc.x = fmaf(q0.x, nj, acc.x);
            acc.y = fmaf(q0.y, nj, acc.y);
            acc.z = fmaf(q1.x, nj, acc.z);
            acc.w = fmaf(q1.y, nj, acc.w);
        }
    }

    float4 bb = __ldg((const float4*)b + lane);
    acc.x += bb.x; acc.y += bb.y; acc.z += bb.z; acc.w += bb.w;
    ((float4*)(ofp + (size_t)row * FDIM))[lane] = acc;
}

// ---------------------------------------------------------------------------
extern "C" void kernel_launch(void* const* d_in, const int* in_sizes, int n_in,
                              void* d_out, int out_size)
{
    const float* x  = (const float*)d_in[0];
    const int*   ei = (const int*)d_in[1];   // int32 (JAX x64 disabled)
    const float* W1 = (const float*)d_in[2];
    const float* b1 = (const float*)d_in[3];
    const float* W2 = (const float*)d_in[4];
    const float* b2 = (const float*)d_in[5];
    const float* W3 = (const float*)d_in[6];
    const float* b3 = (const float*)d_in[7];
    float* out = (float*)d_out;

    int N = in_sizes[0] / FDIM;
    int E = in_sizes[1] / 2;

    __half *HA, *HB, *XH, *WT;
    cudaGetSymbolAddress((void**)&HA, g_hA);
    cudaGetSymbolAddress((void**)&HB, g_hB);
    cudaGetSymbolAddress((void**)&XH, g_xh);
    cudaGetSymbolAddress((void**)&WT, g_wt);
    int* CNT;
    cudaGetSymbolAddress((void**)&CNT, g_cnt);

    cudaFuncSetAttribute(k_gemm1, cudaFuncAttributeMaxDynamicSharedMemorySize, FUSED_SMEM);
    cudaFuncSetAttribute(k_fused, cudaFuncAttributeMaxDynamicSharedMemorySize, FUSED_SMEM);

    int nThr = 256;
    int nBlkN    = (N + nThr - 1) / nThr;
    int nBlkE    = (E + nThr - 1) / nThr;
    int nBlkGemm = (N + 127) / 128;
    int nChunks  = (N + CHUNK - 1) / CHUNK;
    long long gthreads = (long long)N * 32;
    int nBlkGather = (int)((gthreads + nThr - 1) / nThr);
    long long n8 = (long long)N * FDIM / 8;
    int nBlkConv = (int)((n8 + nThr - 1) / nThr);
    const int WSZ = FDIM * FDIM;

    // Fork-join: branch A (converts + gemm1) parallel to branch B (CSR).
    cudaStream_t s2;
    cudaStreamCreateWithFlags(&s2, cudaStreamNonBlocking);
    cudaEvent_t evFork, evA;
    cudaEventCreateWithFlags(&evFork, cudaEventDisableTiming);
    cudaEventCreateWithFlags(&evA, cudaEventDisableTiming);

    cudaEventRecord(evFork, 0);
    cudaStreamWaitEvent(s2, evFork, 0);

    // Branch A (s2): convertX -> convertW -> gemm1 (X @ W1 -> hA)
    k_convertX<<<nBlkConv, nThr, 0, s2>>>(x, n8);
    k_convertW<<<192, nThr, 0, s2>>>(W1, W2, W3);
    k_gemm1<<<nBlkGemm, nThr, FUSED_SMEM, s2>>>(XH, WT, HA, N);
    cudaEventRecord(evA, s2);

    // Branch B (default stream): CSR build
    cudaMemsetAsync(CNT, 0, (size_t)N * sizeof(int));
    k_hist<<<nBlkE, nThr>>>(ei, E);
    k_scan1<<<nChunks, nThr>>>(N);
    k_scan23<<<nBlkN, nThr>>>(N, nChunks);
    k_build<<<nBlkE, nThr>>>(ei, E);

    // Join
    cudaStreamWaitEvent(0, evA, 0);

    // Fused layer boundaries:
    // gather(hA)+b1+relu -> @W2 -> hB
    k_fused<<<nBlkGemm, nThr, FUSED_SMEM>>>(HA, b1, WT + WSZ, HB, N);
    // gather(hB)+b2+relu -> @W3 -> hA
    k_fused<<<nBlkGemm, nThr, FUSED_SMEM>>>(HB, b2, WT + 2*WSZ, HA, N);
    // final gather: hA + b3 -> fp32 out
    k_gather_out<<<nBlkGather, nThr>>>(HA, b3, out, N);

    cudaEventDestroy(evFork);
    cudaEventDestroy(evA);
    cudaStreamDestroy(s2);
}

// round 14
// speedup vs baseline: 1.3907x; 1.3907x over previous
#include <cuda_runtime.h>
#include <cuda_fp16.h>
#include <cstdint>

#define MAX_N 100000
#define MAX_E 1700000
#define FDIM  128
#define CHUNK 1024

// Scratch (allocation-free: __device__ globals)
__device__ __half g_hh[(size_t)MAX_N * FDIM];   // H (fp16)
__device__ __half g_xh[(size_t)MAX_N * FDIM];   // inter-layer X (fp16)
__device__ __half g_wt[3 * FDIM * FDIM];        // W transposed [n][k], fp16
__device__ float g_dinv[MAX_N];
__device__ float g_dinv2[MAX_N];
__device__ int   g_cnt[MAX_N];
__device__ int   g_pos[MAX_N];
__device__ int   g_rowStart[MAX_N];
__device__ int   g_wcur[MAX_N];
__device__ int   g_chunkSum[128];
__device__ int2  g_epk[MAX_E];                  // packed (src, norm-bits)

// ---------------------------------------------------------------------------
__global__ void k_hist(const int* __restrict__ ei, int E) {
    int e = blockIdx.x * blockDim.x + threadIdx.x;
    if (e < E) atomicAdd(&g_cnt[ei[E + e]], 1);
}

__global__ __launch_bounds__(256) void k_scan1(int n) {
    __shared__ int sh[256];
    int t = threadIdx.x;
    int base = blockIdx.x * CHUNK + t * 4;
    int v0 = (base + 0 < n) ? g_cnt[base + 0] : 0;
    int v1 = (base + 1 < n) ? g_cnt[base + 1] : 0;
    int v2 = (base + 2 < n) ? g_cnt[base + 2] : 0;
    int v3 = (base + 3 < n) ? g_cnt[base + 3] : 0;
    int tsum = v0 + v1 + v2 + v3;
    sh[t] = tsum;
    __syncthreads();
    for (int off = 1; off < 256; off <<= 1) {
        int x = (t >= off) ? sh[t - off] : 0;
        __syncthreads();
        sh[t] += x;
        __syncthreads();
    }
    int texcl = sh[t] - tsum;
    if (base + 0 < n) g_pos[base + 0] = texcl;
    if (base + 1 < n) g_pos[base + 1] = texcl + v0;
    if (base + 2 < n) g_pos[base + 2] = texcl + v0 + v1;
    if (base + 3 < n) g_pos[base + 3] = texcl + v0 + v1 + v2;
    if (t == 255) g_chunkSum[blockIdx.x] = sh[255];
}

// Merged scan2+scan3.
__global__ __launch_bounds__(256) void k_scan23(int n, int nChunks) {
    __shared__ int cs[128];
    int t = threadIdx.x;
    if (t < 128) cs[t] = (t < nChunks) ? g_chunkSum[t] : 0;
    __syncthreads();
    if (t < 128) {
        for (int off = 1; off < 128; off <<= 1) {
            int x = (t >= off) ? cs[t - off] : 0;
            __syncthreads();
            cs[t] += x;
            __syncthreads();
        }
    } else {
        for (int off = 1; off < 128; off <<= 1) { __syncthreads(); __syncthreads(); }
    }
    int i = blockIdx.x * 256 + t;
    if (i < n) {
        int c = i / CHUNK;
        int chunkExcl = (c == 0) ? 0 : cs[c - 1];
        int rs = g_pos[i] + chunkExcl;
        g_rowStart[i] = rs;
        g_wcur[i]     = rs;
        float di = rsqrtf((float)g_cnt[i] + 1.0f);
        g_dinv[i]  = di;
        g_dinv2[i] = di * di;
    }
}

__global__ void k_build(const int* __restrict__ ei, int E) {
    int e = blockIdx.x * blockDim.x + threadIdx.x;
    if (e < E) {
        int s = ei[e];
        int d = ei[E + e];
        int p = atomicAdd(&g_wcur[d], 1);
        g_epk[p] = make_int2(s, __float_as_int(g_dinv[s] * g_dinv[d]));
    }
}

// ---------------------------------------------------------------------------
__global__ void k_convertW(const float* __restrict__ W1,
                           const float* __restrict__ W2,
                           const float* __restrict__ W3) {
    int slot = blockIdx.x >> 6;
    const float* W = (slot == 0) ? W1 : (slot == 1) ? W2 : W3;
    int idx = ((blockIdx.x & 63) << 8) + threadIdx.x;
    int n = idx >> 7, k = idx & 127;
    g_wt[slot * FDIM * FDIM + idx] = __float2half_rn(__ldg(&W[k * FDIM + n]));
}

// ---------------------------------------------------------------------------
// MMA helpers
__device__ __forceinline__ void ldsm4(uint32_t* r, uint32_t addr) {
    asm volatile("ldmatrix.sync.aligned.m8n8.x4.shared.b16 {%0,%1,%2,%3}, [%4];"
        : "=r"(r[0]), "=r"(r[1]), "=r"(r[2]), "=r"(r[3]) : "r"(addr));
}
__device__ __forceinline__ void mma16816(float* c, const uint32_t* a, const uint32_t* b) {
    asm volatile(
        "mma.sync.aligned.m16n8k16.row.col.f32.f16.f16.f32 "
        "{%0,%1,%2,%3}, {%4,%5,%6,%7}, {%8,%9}, {%0,%1,%2,%3};"
        : "+f"(c[0]), "+f"(c[1]), "+f"(c[2]), "+f"(c[3])
        : "r"(a[0]), "r"(a[1]), "r"(a[2]), "r"(a[3]), "r"(b[0]), "r"(b[1]));
}

#define APAD 40

// Shared mma mainloop + epilogue over the current smem chunk tiles.
__device__ __forceinline__ void mma_chunk(
    const __half (*a_s)[APAD], const __half (*b_s)[APAD],
    float acc[2][8][4], int wid, int lane)
{
    int warp_m = wid & 3;
    int warp_n = wid >> 2;
#pragma unroll
    for (int s = 0; s < 2; s++) {
        int kb = s * 16;
        uint32_t af[2][4];
#pragma unroll
        for (int mi = 0; mi < 2; mi++) {
            int mrow = warp_m * 32 + mi * 16 + (lane & 15);
            int kcol = kb + ((lane >> 4) << 3);
            ldsm4(af[mi], (uint32_t)__cvta_generic_to_shared(&a_s[mrow][kcol]));
        }
        uint32_t bf[8][2];
#pragma unroll
        for (int nb = 0; nb < 4; nb++) {
            int nrow = warp_n * 64 + nb * 16 + ((lane >> 4) << 3) + (lane & 7);
            int kcol = kb + (((lane >> 3) & 1) << 3);
            uint32_t r[4];
            ldsm4(r, (uint32_t)__cvta_generic_to_shared(&b_s[nrow][kcol]));
            bf[nb*2][0] = r[0]; bf[nb*2][1] = r[1];
            bf[nb*2+1][0] = r[2]; bf[nb*2+1][1] = r[3];
        }
#pragma unroll
        for (int mi = 0; mi < 2; mi++)
#pragma unroll
            for (int nj = 0; nj < 8; nj++)
                mma16816(acc[mi][nj], af[mi], bf[nj]);
    }
}

__device__ __forceinline__ void gemm_epilogue(
    float acc[2][8][4], __half* hdst, int rowbase, int N, int wid, int lane)
{
    int warp_m = wid & 3;
    int warp_n = wid >> 2;
#pragma unroll
    for (int mi = 0; mi < 2; mi++) {
        int r0 = rowbase + warp_m * 32 + mi * 16 + (lane >> 2);
        int r1 = r0 + 8;
#pragma unroll
        for (int nj = 0; nj < 8; nj++) {
            int col = warp_n * 64 + nj * 8 + 2 * (lane & 3);
            if (r0 < N) {
                __half2 p = __floats2half2_rn(acc[mi][nj][0], acc[mi][nj][1]);
                *(__half2*)&hdst[(size_t)r0 * FDIM + col] = p;
            }
            if (r1 < N) {
                __half2 p = __floats2half2_rn(acc[mi][nj][2], acc[mi][nj][3]);
                *(__half2*)&hdst[(size_t)r1 * FDIM + col] = p;
            }
        }
    }
}

// ---------------------------------------------------------------------------
// Layer-1 GEMM reading fp32 X directly (converts in the fill; no convertX pass).
__global__ __launch_bounds__(256) void k_gemm1x(
    const float* __restrict__ X, const __half* __restrict__ Wt,
    __half* __restrict__ hdst, int N)
{
    __shared__ __half a_s[128][APAD];
    __shared__ __half b_s[128][APAD];

    int t = threadIdx.x, wid = t >> 5, lane = t & 31;
    int rowbase = blockIdx.x * 128;

    float acc[2][8][4];
#pragma unroll
    for (int i = 0; i < 2; i++)
#pragma unroll
        for (int j = 0; j < 8; j++)
#pragma unroll
            for (int q = 0; q < 4; q++) acc[i][j][q] = 0.f;

    for (int kc = 0; kc < 128; kc += 32) {
#pragma unroll
        for (int i = 0; i < 2; i++) {
            int idx = t + i * 256;
            int row = idx >> 2;
            int k8  = (idx & 3) * 8;
            int grow = rowbase + row;
            __half h[8];
            if (grow < N) {
                const float4* xp = (const float4*)&X[(size_t)grow * FDIM + kc + k8];
                float4 v0 = __ldg(xp), v1 = __ldg(xp + 1);
                h[0] = __float2half_rn(v0.x); h[1] = __float2half_rn(v0.y);
                h[2] = __float2half_rn(v0.z); h[3] = __float2half_rn(v0.w);
                h[4] = __float2half_rn(v1.x); h[5] = __float2half_rn(v1.y);
                h[6] = __float2half_rn(v1.z); h[7] = __float2half_rn(v1.w);
            } else {
#pragma unroll
                for (int j = 0; j < 8; j++) h[j] = __float2half_rn(0.f);
            }
            *(uint4*)&a_s[row][k8] = *(uint4*)h;
            *(uint4*)&b_s[row][k8] =
                *(const uint4*)&Wt[(size_t)row * FDIM + kc + k8];
        }
        __syncthreads();
        mma_chunk(a_s, b_s, acc, wid, lane);
        __syncthreads();
    }
    gemm_epilogue(acc, hdst, rowbase, N, wid, lane);
}

// ---------------------------------------------------------------------------
// Layers 2/3 GEMM: fp16 in / fp16 out.
__global__ __launch_bounds__(256) void k_gemm(
    const __half* __restrict__ Xh, const __half* __restrict__ Wt,
    __half* __restrict__ hdst, int N)
{
    __shared__ __half a_s[128][APAD];
    __shared__ __half b_s[128][APAD];

    int t = threadIdx.x, wid = t >> 5, lane = t & 31;
    int rowbase = blockIdx.x * 128;

    float acc[2][8][4];
#pragma unroll
    for (int i = 0; i < 2; i++)
#pragma unroll
        for (int j = 0; j < 8; j++)
#pragma unroll
            for (int q = 0; q < 4; q++) acc[i][j][q] = 0.f;

    for (int kc = 0; kc < 128; kc += 32) {
#pragma unroll
        for (int i = 0; i < 2; i++) {
            int idx = t + i * 256;
            int row = idx >> 2;
            int k8  = (idx & 3) * 8;
            int grow = rowbase + row;
            uint4 v = (grow < N)
                ? *(const uint4*)&Xh[(size_t)grow * FDIM + kc + k8]
                : make_uint4(0, 0, 0, 0);
            *(uint4*)&a_s[row][k8] = v;
            *(uint4*)&b_s[row][k8] =
                *(const uint4*)&Wt[(size_t)row * FDIM + kc + k8];
        }
        __syncthreads();
        mma_chunk(a_s, b_s, acc, wid, lane);
        __syncthreads();
    }
    gemm_epilogue(acc, hdst, rowbase, N, wid, lane);
}

// ---------------------------------------------------------------------------
// Pull-based aggregation + self-loop + bias + relu, fused. H fp16, edges int2.
// mode 0: write fp16 into g_xh (feeds next GEMM), relu.
// mode 1: write fp32 to ofp (final layer), no relu.
__global__ __launch_bounds__(256) void k_gather(
    const __half* __restrict__ h, const float* __restrict__ b,
    float* __restrict__ ofp, int N, int mode)
{
    int warp = (blockIdx.x * 256 + threadIdx.x) >> 5;
    int lane = threadIdx.x & 31;
    if (warp >= N) return;

    int row   = warp;
    int start = g_rowStart[row];
    int cnt   = g_cnt[row];

    float d2 = g_dinv2[row];
    uint2 hv = __ldg((const uint2*)(h + (size_t)row * FDIM) + lane);
    float2 p0 = __half22float2(*(__half2*)&hv.x);
    float2 p1 = __half22float2(*(__half2*)&hv.y);
    float4 acc = make_float4(p0.x * d2, p0.y * d2, p1.x * d2, p1.y * d2);

    for (int e0 = 0; e0 < cnt; e0 += 32) {
        int mye = e0 + lane;
        int s = 0; float nm = 0.f;
        if (mye < cnt) {
            int2 ep = __ldg(&g_epk[start + mye]);
            s  = ep.x;
            nm = __int_as_float(ep.y);
        }
        int m = min(32, cnt - e0);
#pragma unroll 8
        for (int j = 0; j < m; j++) {
            int   sj = __shfl_sync(0xffffffffu, s,  j);
            float nj = __shfl_sync(0xffffffffu, nm, j);
            uint2 v = __ldg((const uint2*)(h + (size_t)sj * FDIM) + lane);
            float2 q0 = __half22float2(*(__half2*)&v.x);
            float2 q1 = __half22float2(*(__half2*)&v.y);
            acc.x = fmaf(q0.x, nj, acc.x);
            acc.y = fmaf(q0.y, nj, acc.y);
            acc.z = fmaf(q1.x, nj, acc.z);
            acc.w = fmaf(q1.y, nj, acc.w);
        }
    }

    float4 bb = __ldg((const float4*)b + lane);
    acc.x += bb.x; acc.y += bb.y; acc.z += bb.z; acc.w += bb.w;

    if (mode == 0) {
        __half hh[4];
        hh[0] = __float2half_rn(fmaxf(acc.x, 0.f));
        hh[1] = __float2half_rn(fmaxf(acc.y, 0.f));
        hh[2] = __float2half_rn(fmaxf(acc.z, 0.f));
        hh[3] = __float2half_rn(fmaxf(acc.w, 0.f));
        *(uint2*)&g_xh[(size_t)row * FDIM + lane * 4] = *(uint2*)hh;
    } else {
        ((float4*)(ofp + (size_t)row * FDIM))[lane] = acc;
    }
}

// ---------------------------------------------------------------------------
extern "C" void kernel_launch(void* const* d_in, const int* in_sizes, int n_in,
                              void* d_out, int out_size)
{
    const float* x  = (const float*)d_in[0];
    const int*   ei = (const int*)d_in[1];   // int32 (JAX x64 disabled)
    const float* W1 = (const float*)d_in[2];
    const float* b1 = (const float*)d_in[3];
    const float* W2 = (const float*)d_in[4];
    const float* b2 = (const float*)d_in[5];
    const float* W3 = (const float*)d_in[6];
    const float* b3 = (const float*)d_in[7];
    float* out = (float*)d_out;

    int N = in_sizes[0] / FDIM;
    int E = in_sizes[1] / 2;

    __half *HH, *XH, *WT;
    cudaGetSymbolAddress((void**)&HH, g_hh);
    cudaGetSymbolAddress((void**)&XH, g_xh);
    cudaGetSymbolAddress((void**)&WT, g_wt);
    int* CNT;
    cudaGetSymbolAddress((void**)&CNT, g_cnt);

    int nThr = 256;
    int nBlkN    = (N + nThr - 1) / nThr;
    int nBlkE    = (E + nThr - 1) / nThr;
    int nBlkGemm = (N + 127) / 128;
    int nChunks  = (N + CHUNK - 1) / CHUNK;
    long long gthreads = (long long)N * 32;
    int nBlkGather = (int)((gthreads + nThr - 1) / nThr);
    const int WSZ = FDIM * FDIM;

    // Fork-join: branch A (convertW + gemm1x) parallel to branch B (CSR).
    cudaStream_t s2;
    cudaStreamCreateWithFlags(&s2, cudaStreamNonBlocking);
    cudaEvent_t evFork, evA;
    cudaEventCreateWithFlags(&evFork, cudaEventDisableTiming);
    cudaEventCreateWithFlags(&evA, cudaEventDisableTiming);

    cudaEventRecord(evFork, 0);
    cudaStreamWaitEvent(s2, evFork, 0);

    // Branch A (s2): convertW -> gemm1x (fp32 X @ W1 -> H, conversion fused)
    k_convertW<<<192, nThr, 0, s2>>>(W1, W2, W3);
    k_gemm1x<<<nBlkGemm, nThr, 0, s2>>>(x, WT, HH, N);
    cudaEventRecord(evA, s2);

    // Branch B (default stream): CSR build
    cudaMemsetAsync(CNT, 0, (size_t)N * sizeof(int));
    k_hist<<<nBlkE, nThr>>>(ei, E);
    k_scan1<<<nChunks, nThr>>>(N);
    k_scan23<<<nBlkN, nThr>>>(N, nChunks);
    k_build<<<nBlkE, nThr>>>(ei, E);

    // Join
    cudaStreamWaitEvent(0, evA, 0);

    // Layer 1 gather -> XH
    k_gather<<<nBlkGather, nThr>>>(HH, b1, nullptr, N, 0);

    // Layer 2
    k_gemm<<<nBlkGemm, nThr>>>(XH, WT + WSZ, HH, N);
    k_gather<<<nBlkGather, nThr>>>(HH, b2, nullptr, N, 0);

    // Layer 3: fp32 out, no relu
    k_gemm<<<nBlkGemm, nThr>>>(XH, WT + 2*WSZ, HH, N);
    k_gather<<<nBlkGather, nThr>>>(HH, b3, out, N, 1);

    cudaEventDestroy(evFork);
    cudaEventDestroy(evA);
    cudaStreamDestroy(s2);
}